// round 16
// baseline (speedup 1.0000x reference)
#include <cuda_runtime.h>
#include <cstdint>

#define B_  8
#define C_  64
#define T_  12
#define N_  512
#define G_  (B_ * T_)      // 96
#define H_  4
#define CO_ 64
#define HC_ (H_ * CO_)     // 256
#define NEG_SLOPE 0.2f
#define EMAX 16384

typedef unsigned long long ull;

// ---------------- device scratch ----------------
__device__ float    g_z [(size_t)G_ * N_ * HC_];   // [G,N,256] fp32
__device__ float    g_u[2 * H_ * C_];              // [src/dst][h][c]
__device__ uint4    g_Wp[8192];                    // [kk][q][tig][co] packed (wh,wh+4,wl,wl+4)
__device__ int      g_rowptr[N_ + 1];
__device__ int      g_col[EMAX];

__device__ __forceinline__ float lrelu(float x) {
    return x > 0.0f ? x : NEG_SLOPE * x;
}
__device__ __forceinline__ ull pack2(float lo, float hi) {
    ull d;
    asm("mov.b64 %0, {%1, %2};" : "=l"(d) : "r"(__float_as_uint(lo)), "r"(__float_as_uint(hi)));
    return d;
}
__device__ __forceinline__ void unpack2(ull v, float& lo, float& hi) {
    unsigned a, b;
    asm("mov.b64 {%0, %1}, %2;" : "=r"(a), "=r"(b) : "l"(v));
    lo = __uint_as_float(a); hi = __uint_as_float(b);
}
__device__ __forceinline__ ull fma2(ull a, ull b, ull c) {
    ull d;
    asm("fma.rn.f32x2 %0, %1, %2, %3;" : "=l"(d) : "l"(a), "l"(b), "l"(c));
    return d;
}
__device__ __forceinline__ void tf32_split(float v, unsigned& hi, unsigned& lo) {
    asm("cvt.rna.tf32.f32 %0, %1;" : "=r"(hi) : "f"(v));
    float r = v - __uint_as_float(hi);
    asm("cvt.rna.tf32.f32 %0, %1;" : "=r"(lo) : "f"(r));
}
__device__ __forceinline__ void mma_tf32(float& d0, float& d1, float& d2, float& d3,
                                         unsigned a0, unsigned a1, unsigned a2, unsigned a3,
                                         unsigned b0, unsigned b1) {
    asm volatile("mma.sync.aligned.m16n8k8.row.col.f32.tf32.tf32.f32 "
                 "{%0,%1,%2,%3}, {%4,%5,%6,%7}, {%8,%9}, {%0,%1,%2,%3};"
                 : "+f"(d0), "+f"(d1), "+f"(d2), "+f"(d3)
                 : "r"(a0), "r"(a1), "r"(a2), "r"(a3), "r"(b0), "r"(b1));
}
__device__ __forceinline__ void cp_async16(uint32_t smem_addr, const void* gptr) {
    asm volatile("cp.async.cg.shared.global [%0], [%1], 16;"
                 :: "r"(smem_addr), "l"(gptr) : "memory");
}

// ============================================================
// K0: setup. block 0: CSR build. block 1: prep u + packed W. 512 thr.
// ============================================================
__global__ void setup_kernel(const int* __restrict__ ei, int E,
                             const float* __restrict__ W,
                             const float* __restrict__ att_src,
                             const float* __restrict__ att_dst) {
    int tid = threadIdx.x;
    if (blockIdx.x == 0) {
        __shared__ int cnt[N_];
        __shared__ int cur[N_];
        __shared__ int wsum[16];
        cnt[tid] = 0;
        __syncthreads();
        const int* dst = ei + E;
        for (int e = tid; e < E; e += N_) atomicAdd(&cnt[dst[e]], 1);
        __syncthreads();

        int v = cnt[tid];
        int lane = tid & 31, wid = tid >> 5;
        int inc = v;
        #pragma unroll
        for (int o = 1; o < 32; o <<= 1) {
            int u = __shfl_up_sync(0xffffffffu, inc, o);
            if (lane >= o) inc += u;
        }
        if (lane == 31) wsum[wid] = inc;
        __syncthreads();
        if (wid == 0 && lane < 16) {
            int ws = wsum[lane];
            int wi = ws;
            #pragma unroll
            for (int o = 1; o < 16; o <<= 1) {
                int u = __shfl_up_sync(0x0000ffffu, wi, o);
                if (lane >= o) wi += u;
            }
            wsum[lane] = wi - ws;
        }
        __syncthreads();
        int excl = inc - v + wsum[wid];
        g_rowptr[tid] = excl;
        cur[tid] = excl;
        if (tid == N_ - 1) g_rowptr[N_] = excl + v;
        __syncthreads();

        for (int e = tid; e < E; e += N_) {
            int d = dst[e];
            int p = atomicAdd(&cur[d], 1);
            g_col[p] = ei[e];
        }
    } else {
        __shared__ float satt[2 * H_ * CO_];
        satt[tid] = (tid < 256) ? att_src[tid] : att_dst[tid - 256];
        __syncthreads();

        {
            int k = tid;                 // 512 = 2*4*64
            int p = k >> 8;
            int h = (k >> 6) & 3;
            int c = k & 63;
            const float* wrow = W + (size_t)c * HC_ + h * CO_;
            const float* av = satt + p * 256 + h * CO_;
            float s = 0.0f;
            #pragma unroll 16
            for (int co = 0; co < CO_; co++) s += wrow[co] * av[co];
            g_u[k] = s;
        }
        // packed W: g_Wp[((kk*4+q)*4+tig)*64+co] = (wh[k],wh[k+4],wl[k],wl[k+4]),
        // k = kk*32 + q*8 + tig, wt = 0.25*W[c][h*64+co] with k = h*64+c
        for (int idx = tid; idx < 8192; idx += 512) {
            int co  = idx & 63;
            int tig = (idx >> 6) & 3;
            int q   = (idx >> 8) & 3;
            int kk  = idx >> 10;
            int k   = kk * 32 + q * 8 + tig;
            int h  = k >> 6,  c  = k & 63;
            int k2 = k + 4;
            int h2 = k2 >> 6, c2 = k2 & 63;
            float w0 = 0.25f * W[(size_t)c  * HC_ + h  * CO_ + co];
            float w1 = 0.25f * W[(size_t)c2 * HC_ + h2 * CO_ + co];
            uint4 pv;
            tf32_split(w0, pv.x, pv.z);
            tf32_split(w1, pv.y, pv.w);
            g_Wp[idx] = pv;
        }
    }
}

// ============================================================
// K1: FUSED per-graph kernel: x -> smem xt, asrc/adst, edge-softmax
// aggregate, all on-chip. One CTA per g. 512 threads, ~168 KB smem.
// ============================================================
#define XPITCH 66                       // even (8B-aligned rows); fill 2-way ok
#define XT_F   (N_ * XPITCH)            // 33792 floats
#define AS_F   (N_ * 4)                 // 2048
#define FUSED_F (XT_F + 2*AS_F + 512 + 4096 + 512)   // + s_u + s_wp(2048 ull) + s_src
#define FUSED_SMEM (FUSED_F * 4)        // 172032 B

__global__ void __launch_bounds__(512) fused_agg_kernel(const float* __restrict__ x) {
    extern __shared__ __align__(16) float sm[];
    float*  xt    = sm;                                   // [512][66]
    float4* s_as  = (float4*)(sm + XT_F);                 // [512]
    float4* s_ad  = (float4*)(sm + XT_F + AS_F);          // [512]
    float*  s_u   = sm + XT_F + 2 * AS_F;                 // [512]
    ull*    s_wp  = (ull*)(sm + XT_F + 2 * AS_F + 512);   // [16][32][4]
    int*    s_src = (int*)(sm + XT_F + 2 * AS_F + 512 + 4096);  // [16][32]

    int tid = threadIdx.x;
    int g = blockIdx.x;
    int b = g / T_, t = g - b * T_;

    s_u[tid] = g_u[tid];

    // fill xt[n][c] from x[b][c][t][n]; coalesced gmem reads,
    // STS banks (2n + c): consecutive n within warp -> 2-way (acceptable)
    for (int i = tid; i < C_ * N_; i += 512) {
        int c = i >> 9, n = i & 511;
        xt[n * XPITCH + c] = x[(((size_t)b * C_ + c) * T_ + t) * N_ + n];
    }
    __syncthreads();

    // asrc/adst: thread per n
    {
        int n = tid;
        const float* row = xt + n * XPITCH;
        float a0 = 0.f, a1 = 0.f, a2 = 0.f, a3 = 0.f;
        float d0 = 0.f, d1 = 0.f, d2 = 0.f, d3 = 0.f;
        #pragma unroll 8
        for (int c = 0; c < 64; c++) {
            float xv = row[c];
            a0 = fmaf(xv, s_u[c      ], a0);
            a1 = fmaf(xv, s_u[64  + c], a1);
            a2 = fmaf(xv, s_u[128 + c], a2);
            a3 = fmaf(xv, s_u[192 + c], a3);
            d0 = fmaf(xv, s_u[256 + c], d0);
            d1 = fmaf(xv, s_u[320 + c], d1);
            d2 = fmaf(xv, s_u[384 + c], d2);
            d3 = fmaf(xv, s_u[448 + c], d3);
        }
        s_as[n] = make_float4(a0, a1, a2, a3);
        s_ad[n] = make_float4(d0, d1, d2, d3);
    }
    __syncthreads();

    // aggregate: warp per dst, smem gather. 16 warps x 32 rounds.
    int warp = tid >> 5, lane = tid & 31;
    const ull* xtu = (const ull*)xt;     // row pitch 33 ull
    ull* wp = s_wp + (warp * 32 + 0) * 4;
    int* sp = s_src + warp * 32;

    for (int dst = warp; dst < N_; dst += 16) {
        int start = g_rowptr[dst];
        int end   = g_rowptr[dst + 1];

        float4 ad = s_ad[dst];
        float4 sa = s_as[dst];
        float ws0 = __expf(lrelu(sa.x + ad.x));
        float ws1 = __expf(lrelu(sa.y + ad.y));
        float ws2 = __expf(lrelu(sa.z + ad.z));
        float ws3 = __expf(lrelu(sa.w + ad.w));

        ull xdv = xtu[(size_t)dst * (XPITCH / 2) + lane];
        ull acc0 = fma2(pack2(ws0, ws0), xdv, 0ULL);
        ull acc1 = fma2(pack2(ws1, ws1), xdv, 0ULL);
        ull acc2 = fma2(pack2(ws2, ws2), xdv, 0ULL);
        ull acc3 = fma2(pack2(ws3, ws3), xdv, 0ULL);

        float p0 = 0.f, p1 = 0.f, p2 = 0.f, p3 = 0.f;

        for (int base = start; base < end; base += 32) {
            int e = base + lane;
            int src = 0;
            float w0 = 0.f, w1 = 0.f, w2 = 0.f, w3 = 0.f;
            if (e < end) {
                src = g_col[e];
                float4 a = s_as[src];
                w0 = __expf(lrelu(a.x + ad.x));
                w1 = __expf(lrelu(a.y + ad.y));
                w2 = __expf(lrelu(a.z + ad.z));
                w3 = __expf(lrelu(a.w + ad.w));
            }
            p0 += w0; p1 += w1; p2 += w2; p3 += w3;
            ulonglong2 pA, pB;
            pA.x = pack2(w0, w0); pA.y = pack2(w1, w1);
            pB.x = pack2(w2, w2); pB.y = pack2(w3, w3);
            *(ulonglong2*)&wp[lane * 4]     = pA;
            *(ulonglong2*)&wp[lane * 4 + 2] = pB;
            sp[lane] = src;
            __syncwarp();

            int cnt = min(32, end - base);
            int sj = sp[0];
            ull xv = xtu[(size_t)sj * (XPITCH / 2) + lane];
            for (int j = 0; j < cnt; j++) {
                int jn = min(j + 1, cnt - 1);
                int sn = sp[jn];
                ull xn = xtu[(size_t)sn * (XPITCH / 2) + lane];
                ulonglong2 wA = *(const ulonglong2*)&wp[j * 4];
                ulonglong2 wB = *(const ulonglong2*)&wp[j * 4 + 2];
                acc0 = fma2(wA.x, xv, acc0);
                acc1 = fma2(wA.y, xv, acc1);
                acc2 = fma2(wB.x, xv, acc2);
                acc3 = fma2(wB.y, xv, acc3);
                xv = xn;
            }
            __syncwarp();
        }

        #pragma unroll
        for (int o = 16; o > 0; o >>= 1) {
            p0 += __shfl_xor_sync(0xffffffffu, p0, o);
            p1 += __shfl_xor_sync(0xffffffffu, p1, o);
            p2 += __shfl_xor_sync(0xffffffffu, p2, o);
            p3 += __shfl_xor_sync(0xffffffffu, p3, o);
        }
        float i0 = 1.0f / (p0 + ws0);
        float i1 = 1.0f / (p1 + ws1);
        float i2 = 1.0f / (p2 + ws2);
        float i3 = 1.0f / (p3 + ws3);

        float lo, hi;
        float* zp = g_z + ((size_t)g * N_ + dst) * HC_ + 2 * lane;
        unpack2(acc0, lo, hi); *(float2*)(zp +   0) = make_float2(lo * i0, hi * i0);
        unpack2(acc1, lo, hi); *(float2*)(zp +  64) = make_float2(lo * i1, hi * i1);
        unpack2(acc2, lo, hi); *(float2*)(zp + 128) = make_float2(lo * i2, hi * i2);
        unpack2(acc3, lo, hi); *(float2*)(zp + 192) = make_float2(lo * i3, hi * i3);
    }
}

// ============================================================
// K2: out = z @ Wt + bias -> [B,Co,T,N], tensor cores.
// 2-stage cp.async pipeline (unchanged from R15).
// ============================================================
#define KCH 32
#define Z_ELEMS (128 * 36)
#define Z_BYTES (Z_ELEMS * 4)
#define W_ELEMS (4 * 4 * 66)
#define W_BYTES (W_ELEMS * 16)
#define STAGE_BYTES (Z_BYTES + W_BYTES)

__global__ void __launch_bounds__(256, 3) gemm2_tc_kernel(const float* __restrict__ bias,
                                                          float* __restrict__ out) {
    extern __shared__ __align__(16) char dsm[];

    int g   = blockIdx.y;
    int qt  = blockIdx.x;
    int b   = g / T_;
    int t   = g - b * T_;
    int tid = threadIdx.x;
    int w    = tid >> 5;
    int lane = tid & 31;
    int gid  = lane >> 2;
    int tig  = lane & 3;

    float acc[8][4];
    #pragma unroll
    for (int ct = 0; ct < 8; ct++)
        #pragma unroll
        for (int j = 0; j < 4; j++) acc[ct][j] = 0.0f;

    const float* zbase = g_z + ((size_t)g * N_ + qt * 128) * HC_;

    auto issue_chunk = [&](int kk, int s) {
        char* sb = dsm + s * STAGE_BYTES;
        float* s_z = (float*)sb;
        uint4* s_w = (uint4*)(sb + Z_BYTES);
        #pragma unroll
        for (int j = 0; j < 4; j++) {
            int i = tid + 256 * j;
            int n = i >> 3, q4 = i & 7;
            uint32_t dst = (uint32_t)__cvta_generic_to_shared(&s_z[n * 36 + q4 * 4]);
            cp_async16(dst, zbase + (size_t)n * HC_ + kk * KCH + q4 * 4);
        }
        #pragma unroll
        for (int j = 0; j < 4; j++) {
            int idx = tid + 256 * j;
            int co = idx & 63, tg = (idx >> 6) & 3, q = idx >> 8;
            uint32_t dst = (uint32_t)__cvta_generic_to_shared(&s_w[(q * 4 + tg) * 66 + co]);
            cp_async16(dst, g_Wp + kk * 1024 + idx);
        }
        asm volatile("cp.async.commit_group;" ::: "memory");
    };

    issue_chunk(0, 0);

    for (int kk = 0; kk < HC_ / KCH; kk++) {
        asm volatile("cp.async.wait_group 0;" ::: "memory");
        __syncthreads();
        if (kk + 1 < HC_ / KCH) issue_chunk(kk + 1, (kk + 1) & 1);

        char* sb = dsm + (kk & 1) * STAGE_BYTES;
        float* s_z = (float*)sb;
        uint4* s_w = (uint4*)(sb + Z_BYTES);

        #pragma unroll
        for (int q = 0; q < 4; q++) {
            int k0 = q * 8;
            int rb = w * 16 + gid;
            unsigned ah0, ah1, ah2, ah3, al0, al1, al2, al3;
            tf32_split(s_z[(rb    ) * 36 + k0 + tig    ], ah0, al0);
            tf32_split(s_z[(rb + 8) * 36 + k0 + tig    ], ah1, al1);
            tf32_split(s_z[(rb    ) * 36 + k0 + tig + 4], ah2, al2);
            tf32_split(s_z[(rb + 8) * 36 + k0 + tig + 4], ah3, al3);
            #pragma unroll
            for (int ct = 0; ct < 8; ct++) {
                uint4 wv = s_w[(q * 4 + tig) * 66 + ct * 8 + gid];
                mma_tf32(acc[ct][0], acc[ct][1], acc[ct][2], acc[ct][3],
                         ah0, ah1, ah2, ah3, wv.x, wv.y);
                mma_tf32(acc[ct][0], acc[ct][1], acc[ct][2], acc[ct][3],
                         al0, al1, al2, al3, wv.x, wv.y);
                mma_tf32(acc[ct][0], acc[ct][1], acc[ct][2], acc[ct][3],
                         ah0, ah1, ah2, ah3, wv.z, wv.w);
            }
        }
    }

    int n_g = qt * 128 + w * 16 + gid;
    #pragma unroll
    for (int ct = 0; ct < 8; ct++) {
        int co = ct * 8 + 2 * tig;
        float bv0 = __ldg(&bias[co]);
        float bv1 = __ldg(&bias[co + 1]);
        float* o0 = out + (((size_t)b * CO_ + co)     * T_ + t) * N_ + n_g;
        float* o1 = out + (((size_t)b * CO_ + co + 1) * T_ + t) * N_ + n_g;
        o0[0] = acc[ct][0] + bv0;
        o1[0] = acc[ct][1] + bv1;
        o0[8] = acc[ct][2] + bv0;
        o1[8] = acc[ct][3] + bv1;
    }
}

// ============================================================
extern "C" void kernel_launch(void* const* d_in, const int* in_sizes, int n_in,
                              void* d_out, int out_size) {
    const float* x        = (const float*)d_in[0];
    const int*   ei       = (const int*)  d_in[1];
    const float* W        = (const float*)d_in[2];
    const float* att_src  = (const float*)d_in[3];
    const float* att_dst  = (const float*)d_in[4];
    const float* bias     = (const float*)d_in[5];
    float*       out      = (float*)d_out;
    int E = in_sizes[1] / 2;

    cudaFuncSetAttribute(fused_agg_kernel,
                         cudaFuncAttributeMaxDynamicSharedMemorySize, FUSED_SMEM);
    cudaFuncSetAttribute(gemm2_tc_kernel,
                         cudaFuncAttributeMaxDynamicSharedMemorySize, 2 * STAGE_BYTES);

    setup_kernel<<<2, 512>>>(ei, E, W, att_src, att_dst);
    fused_agg_kernel<<<G_, 512, FUSED_SMEM>>>(x);
    gemm2_tc_kernel<<<dim3(N_ / 128, G_), 256, 2 * STAGE_BYTES>>>(bias, out);
}

// round 17
// speedup vs baseline: 1.1961x; 1.1961x over previous
#include <cuda_runtime.h>
#include <cstdint>

#define B_  8
#define C_  64
#define T_  12
#define N_  512
#define G_  (B_ * T_)      // 96
#define H_  4
#define CO_ 64
#define HC_ (H_ * CO_)     // 256
#define NEG_SLOPE 0.2f
#define EMAX 16384

typedef unsigned long long ull;

// ---------------- device scratch ----------------
__device__ float    g_xt[(size_t)G_ * N_ * C_];    // [G,N,64]
__device__ float    g_z [(size_t)G_ * N_ * HC_];   // [G,N,256] fp32
__device__ float    g_asrc[(size_t)G_ * N_ * H_];  // [G,N,4]
__device__ float    g_adst[(size_t)G_ * N_ * H_];
__device__ float    g_u[2 * H_ * C_];              // [src/dst][h][c]
__device__ uint4    g_Wp[8192];                    // [kk][q][tig][co] packed (wh,wh+4,wl,wl+4)
__device__ int      g_rowptr[N_ + 1];
__device__ int      g_col[EMAX];

__device__ __forceinline__ float lrelu(float x) {
    return x > 0.0f ? x : NEG_SLOPE * x;
}
__device__ __forceinline__ ull pack2(float lo, float hi) {
    ull d;
    asm("mov.b64 %0, {%1, %2};" : "=l"(d) : "r"(__float_as_uint(lo)), "r"(__float_as_uint(hi)));
    return d;
}
__device__ __forceinline__ void unpack2(ull v, float& lo, float& hi) {
    unsigned a, b;
    asm("mov.b64 {%0, %1}, %2;" : "=r"(a), "=r"(b) : "l"(v));
    lo = __uint_as_float(a); hi = __uint_as_float(b);
}
__device__ __forceinline__ ull fma2(ull a, ull b, ull c) {
    ull d;
    asm("fma.rn.f32x2 %0, %1, %2, %3;" : "=l"(d) : "l"(a), "l"(b), "l"(c));
    return d;
}
__device__ __forceinline__ void tf32_split(float v, unsigned& hi, unsigned& lo) {
    asm("cvt.rna.tf32.f32 %0, %1;" : "=r"(hi) : "f"(v));
    float r = v - __uint_as_float(hi);
    asm("cvt.rna.tf32.f32 %0, %1;" : "=r"(lo) : "f"(r));
}
__device__ __forceinline__ void mma_tf32(float& d0, float& d1, float& d2, float& d3,
                                         unsigned a0, unsigned a1, unsigned a2, unsigned a3,
                                         unsigned b0, unsigned b1) {
    asm volatile("mma.sync.aligned.m16n8k8.row.col.f32.tf32.tf32.f32 "
                 "{%0,%1,%2,%3}, {%4,%5,%6,%7}, {%8,%9}, {%0,%1,%2,%3};"
                 : "+f"(d0), "+f"(d1), "+f"(d2), "+f"(d3)
                 : "r"(a0), "r"(a1), "r"(a2), "r"(a3), "r"(b0), "r"(b1));
}
__device__ __forceinline__ void cp_async16(uint32_t smem_addr, const void* gptr) {
    asm volatile("cp.async.cg.shared.global [%0], [%1], 16;"
                 :: "r"(smem_addr), "l"(gptr) : "memory");
}

// ============================================================
// K0: setup, 41 blocks x 512 threads.
//  block 0      : CSR build
//  blocks 1-32  : u, one warp per output (coalesced W reads)
//  blocks 33-40 : Wp packing, 1024 elements per block
// ============================================================
__global__ void setup_kernel(const int* __restrict__ ei, int E,
                             const float* __restrict__ W,
                             const float* __restrict__ att_src,
                             const float* __restrict__ att_dst) {
    int tid = threadIdx.x;
    int bk  = blockIdx.x;
    if (bk == 0) {
        __shared__ int cnt[N_];
        __shared__ int cur[N_];
        __shared__ int wsum[16];
        cnt[tid] = 0;
        __syncthreads();
        const int* dst = ei + E;
        for (int e = tid; e < E; e += N_) atomicAdd(&cnt[dst[e]], 1);
        __syncthreads();

        int v = cnt[tid];
        int lane = tid & 31, wid = tid >> 5;
        int inc = v;
        #pragma unroll
        for (int o = 1; o < 32; o <<= 1) {
            int u = __shfl_up_sync(0xffffffffu, inc, o);
            if (lane >= o) inc += u;
        }
        if (lane == 31) wsum[wid] = inc;
        __syncthreads();
        if (wid == 0 && lane < 16) {
            int ws = wsum[lane];
            int wi = ws;
            #pragma unroll
            for (int o = 1; o < 16; o <<= 1) {
                int u = __shfl_up_sync(0x0000ffffu, wi, o);
                if (lane >= o) wi += u;
            }
            wsum[lane] = wi - ws;
        }
        __syncthreads();
        int excl = inc - v + wsum[wid];
        g_rowptr[tid] = excl;
        cur[tid] = excl;
        if (tid == N_ - 1) g_rowptr[N_] = excl + v;
        __syncthreads();

        for (int e = tid; e < E; e += N_) {
            int d = dst[e];
            int p = atomicAdd(&cur[d], 1);
            g_col[p] = ei[e];
        }
    } else if (bk <= 32) {
        // u: warp per output. k = (bk-1)*16 + warp
        int warp = tid >> 5, lane = tid & 31;
        int k = (bk - 1) * 16 + warp;         // 0..511
        int p = k >> 8;
        int h = (k >> 6) & 3;
        int c = k & 63;
        float2 wv = *(const float2*)(W + (size_t)c * HC_ + h * CO_ + lane * 2);
        const float* av = (p == 0 ? att_src : att_dst) + h * CO_ + lane * 2;
        float s = wv.x * av[0] + wv.y * av[1];
        #pragma unroll
        for (int o = 16; o > 0; o >>= 1) s += __shfl_xor_sync(0xffffffffu, s, o);
        if (lane == 0) g_u[k] = s;
    } else {
        // Wp: blocks 33..40, 1024 elements each, 2 per thread
        int base = (bk - 33) * 1024;
        #pragma unroll
        for (int r = 0; r < 2; r++) {
            int idx = base + tid + r * 512;
            int co  = idx & 63;
            int tig = (idx >> 6) & 3;
            int q   = (idx >> 8) & 3;
            int kk  = idx >> 10;
            int k   = kk * 32 + q * 8 + tig;
            int h  = k >> 6,  c  = k & 63;
            int k2 = k + 4;
            int h2 = k2 >> 6, c2 = k2 & 63;
            float w0 = 0.25f * W[(size_t)c  * HC_ + h  * CO_ + co];
            float w1 = 0.25f * W[(size_t)c2 * HC_ + h2 * CO_ + co];
            uint4 pv;
            tf32_split(w0, pv.x, pv.z);
            tf32_split(w1, pv.y, pv.w);
            g_Wp[idx] = pv;
        }
    }
}

// ============================================================
// K1: per g: transpose x -> xt, asrc/adst = x . u
// grid (4, 96), block 256.  (R15, proven)
// ============================================================
__global__ void xt_asrc_kernel(const float* __restrict__ x) {
    __shared__ float xs[64][129];
    __shared__ float su[8][64];
    int g  = blockIdx.y;
    int n0 = blockIdx.x * 128;
    int b  = g / T_;
    int t  = g - b * T_;
    int tid = threadIdx.x;

    for (int i = tid; i < 512; i += 256) su[i >> 6][i & 63] = g_u[i];
    #pragma unroll
    for (int i = tid; i < 64 * 32; i += 256) {
        int c = i >> 5, q = i & 31;
        float4 v = *(const float4*)(x + (((size_t)b * C_ + c) * T_ + t) * N_ + n0 + q * 4);
        xs[c][q * 4 + 0] = v.x; xs[c][q * 4 + 1] = v.y;
        xs[c][q * 4 + 2] = v.z; xs[c][q * 4 + 3] = v.w;
    }
    __syncthreads();

    {
        int n = tid & 127;
        int p = tid >> 7;
        float a0 = 0.f, a1 = 0.f, a2 = 0.f, a3 = 0.f;
        #pragma unroll 16
        for (int c = 0; c < 64; c++) {
            float xv = xs[c][n];
            a0 = fmaf(xv, su[p * 4 + 0][c], a0);
            a1 = fmaf(xv, su[p * 4 + 1][c], a1);
            a2 = fmaf(xv, su[p * 4 + 2][c], a2);
            a3 = fmaf(xv, su[p * 4 + 3][c], a3);
        }
        float* dstp = (p == 0 ? g_asrc : g_adst) + ((size_t)g * N_ + n0 + n) * H_;
        dstp[0] = a0; dstp[1] = a1; dstp[2] = a2; dstp[3] = a3;
    }

    #pragma unroll
    for (int i = tid; i < 128 * 16; i += 256) {
        int n = i >> 4, q = i & 15;
        float4 v = {xs[q * 4 + 0][n], xs[q * 4 + 1][n], xs[q * 4 + 2][n], xs[q * 4 + 3][n]};
        *(float4*)(g_xt + ((size_t)g * N_ + n0 + n) * C_ + q * 4) = v;
    }
}

// ============================================================
// K2: aggregate in x-space, warp per (g,dst). (R15, proven)
// ============================================================
__global__ void __launch_bounds__(256) aggregate_kernel() {
    __shared__ float4 s_as[N_];
    __shared__ ull    s_wp[8][32][4];
    __shared__ int    s_src[8][32];
    int g    = blockIdx.y;
    int tid  = threadIdx.x;
    int warp = tid >> 5, lane = tid & 31;

    const float4* asrc_g = (const float4*)(g_asrc + (size_t)g * N_ * H_);
    for (int i = tid; i < N_; i += 256) s_as[i] = asrc_g[i];
    __syncthreads();

    int dst   = (blockIdx.x << 3) + warp;
    int start = g_rowptr[dst];
    int end   = g_rowptr[dst + 1];

    float4 ad = *(const float4*)(g_adst + ((size_t)g * N_ + dst) * H_);
    float4 sa = s_as[dst];
    float ws0 = __expf(lrelu(sa.x + ad.x));
    float ws1 = __expf(lrelu(sa.y + ad.y));
    float ws2 = __expf(lrelu(sa.z + ad.z));
    float ws3 = __expf(lrelu(sa.w + ad.w));

    const ull* xgu = (const ull*)(g_xt + (size_t)g * N_ * C_);

    ull xdv = xgu[(size_t)dst * 32 + lane];
    ull acc0 = fma2(pack2(ws0, ws0), xdv, 0ULL);
    ull acc1 = fma2(pack2(ws1, ws1), xdv, 0ULL);
    ull acc2 = fma2(pack2(ws2, ws2), xdv, 0ULL);
    ull acc3 = fma2(pack2(ws3, ws3), xdv, 0ULL);

    float p0 = 0.f, p1 = 0.f, p2 = 0.f, p3 = 0.f;

    for (int base = start; base < end; base += 32) {
        int e = base + lane;
        int src = 0;
        float w0 = 0.f, w1 = 0.f, w2 = 0.f, w3 = 0.f;
        if (e < end) {
            src = g_col[e];
            float4 a = s_as[src];
            w0 = __expf(lrelu(a.x + ad.x));
            w1 = __expf(lrelu(a.y + ad.y));
            w2 = __expf(lrelu(a.z + ad.z));
            w3 = __expf(lrelu(a.w + ad.w));
        }
        p0 += w0; p1 += w1; p2 += w2; p3 += w3;
        ulonglong2 pA, pB;
        pA.x = pack2(w0, w0); pA.y = pack2(w1, w1);
        pB.x = pack2(w2, w2); pB.y = pack2(w3, w3);
        *(ulonglong2*)&s_wp[warp][lane][0] = pA;
        *(ulonglong2*)&s_wp[warp][lane][2] = pB;
        s_src[warp][lane] = src;
        __syncwarp();

        int cnt = min(32, end - base);
        int sj = s_src[warp][0];
        ull xv = xgu[(size_t)sj * 32 + lane];
        for (int j = 0; j < cnt; j++) {
            int jn = min(j + 1, cnt - 1);
            int sn = s_src[warp][jn];
            ull xn = xgu[(size_t)sn * 32 + lane];
            ulonglong2 wA = *(const ulonglong2*)&s_wp[warp][j][0];
            ulonglong2 wB = *(const ulonglong2*)&s_wp[warp][j][2];
            acc0 = fma2(wA.x, xv, acc0);
            acc1 = fma2(wA.y, xv, acc1);
            acc2 = fma2(wB.x, xv, acc2);
            acc3 = fma2(wB.y, xv, acc3);
            xv = xn;
        }
        __syncwarp();
    }

    #pragma unroll
    for (int o = 16; o > 0; o >>= 1) {
        p0 += __shfl_xor_sync(0xffffffffu, p0, o);
        p1 += __shfl_xor_sync(0xffffffffu, p1, o);
        p2 += __shfl_xor_sync(0xffffffffu, p2, o);
        p3 += __shfl_xor_sync(0xffffffffu, p3, o);
    }
    float i0 = 1.0f / (p0 + ws0);
    float i1 = 1.0f / (p1 + ws1);
    float i2 = 1.0f / (p2 + ws2);
    float i3 = 1.0f / (p3 + ws3);

    float lo, hi;
    float* zp = g_z + ((size_t)g * N_ + dst) * HC_ + 2 * lane;
    unpack2(acc0, lo, hi); *(float2*)(zp +   0) = make_float2(lo * i0, hi * i0);
    unpack2(acc1, lo, hi); *(float2*)(zp +  64) = make_float2(lo * i1, hi * i1);
    unpack2(acc2, lo, hi); *(float2*)(zp + 128) = make_float2(lo * i2, hi * i2);
    unpack2(acc3, lo, hi); *(float2*)(zp + 192) = make_float2(lo * i3, hi * i3);
}

// ============================================================
// K3: out = z @ Wt + bias -> [B,Co,T,N], tensor cores.
// 2-stage cp.async pipeline (R15, proven).
// ============================================================
#define KCH 32
#define Z_ELEMS (128 * 36)
#define Z_BYTES (Z_ELEMS * 4)
#define W_ELEMS (4 * 4 * 66)
#define W_BYTES (W_ELEMS * 16)
#define STAGE_BYTES (Z_BYTES + W_BYTES)

__global__ void __launch_bounds__(256, 3) gemm2_tc_kernel(const float* __restrict__ bias,
                                                          float* __restrict__ out) {
    extern __shared__ __align__(16) char dsm[];

    int g   = blockIdx.y;
    int qt  = blockIdx.x;
    int b   = g / T_;
    int t   = g - b * T_;
    int tid = threadIdx.x;
    int w    = tid >> 5;
    int lane = tid & 31;
    int gid  = lane >> 2;
    int tig  = lane & 3;

    float acc[8][4];
    #pragma unroll
    for (int ct = 0; ct < 8; ct++)
        #pragma unroll
        for (int j = 0; j < 4; j++) acc[ct][j] = 0.0f;

    const float* zbase = g_z + ((size_t)g * N_ + qt * 128) * HC_;

    auto issue_chunk = [&](int kk, int s) {
        char* sb = dsm + s * STAGE_BYTES;
        float* s_z = (float*)sb;
        uint4* s_w = (uint4*)(sb + Z_BYTES);
        #pragma unroll
        for (int j = 0; j < 4; j++) {
            int i = tid + 256 * j;
            int n = i >> 3, q4 = i & 7;
            uint32_t dst = (uint32_t)__cvta_generic_to_shared(&s_z[n * 36 + q4 * 4]);
            cp_async16(dst, zbase + (size_t)n * HC_ + kk * KCH + q4 * 4);
        }
        #pragma unroll
        for (int j = 0; j < 4; j++) {
            int idx = tid + 256 * j;
            int co = idx & 63, tg = (idx >> 6) & 3, q = idx >> 8;
            uint32_t dst = (uint32_t)__cvta_generic_to_shared(&s_w[(q * 4 + tg) * 66 + co]);
            cp_async16(dst, g_Wp + kk * 1024 + idx);
        }
        asm volatile("cp.async.commit_group;" ::: "memory");
    };

    issue_chunk(0, 0);

    for (int kk = 0; kk < HC_ / KCH; kk++) {
        asm volatile("cp.async.wait_group 0;" ::: "memory");
        __syncthreads();
        if (kk + 1 < HC_ / KCH) issue_chunk(kk + 1, (kk + 1) & 1);

        char* sb = dsm + (kk & 1) * STAGE_BYTES;
        float* s_z = (float*)sb;
        uint4* s_w = (uint4*)(sb + Z_BYTES);

        #pragma unroll
        for (int q = 0; q < 4; q++) {
            int k0 = q * 8;
            int rb = w * 16 + gid;
            unsigned ah0, ah1, ah2, ah3, al0, al1, al2, al3;
            tf32_split(s_z[(rb    ) * 36 + k0 + tig    ], ah0, al0);
            tf32_split(s_z[(rb + 8) * 36 + k0 + tig    ], ah1, al1);
            tf32_split(s_z[(rb    ) * 36 + k0 + tig + 4], ah2, al2);
            tf32_split(s_z[(rb + 8) * 36 + k0 + tig + 4], ah3, al3);
            #pragma unroll
            for (int ct = 0; ct < 8; ct++) {
                uint4 wv = s_w[(q * 4 + tig) * 66 + ct * 8 + gid];
                mma_tf32(acc[ct][0], acc[ct][1], acc[ct][2], acc[ct][3],
                         ah0, ah1, ah2, ah3, wv.x, wv.y);
                mma_tf32(acc[ct][0], acc[ct][1], acc[ct][2], acc[ct][3],
                         al0, al1, al2, al3, wv.x, wv.y);
                mma_tf32(acc[ct][0], acc[ct][1], acc[ct][2], acc[ct][3],
                         ah0, ah1, ah2, ah3, wv.z, wv.w);
            }
        }
    }

    int n_g = qt * 128 + w * 16 + gid;
    #pragma unroll
    for (int ct = 0; ct < 8; ct++) {
        int co = ct * 8 + 2 * tig;
        float bv0 = __ldg(&bias[co]);
        float bv1 = __ldg(&bias[co + 1]);
        float* o0 = out + (((size_t)b * CO_ + co)     * T_ + t) * N_ + n_g;
        float* o1 = out + (((size_t)b * CO_ + co + 1) * T_ + t) * N_ + n_g;
        o0[0] = acc[ct][0] + bv0;
        o1[0] = acc[ct][1] + bv1;
        o0[8] = acc[ct][2] + bv0;
        o1[8] = acc[ct][3] + bv1;
    }
}

// ============================================================
extern "C" void kernel_launch(void* const* d_in, const int* in_sizes, int n_in,
                              void* d_out, int out_size) {
    const float* x        = (const float*)d_in[0];
    const int*   ei       = (const int*)  d_in[1];
    const float* W        = (const float*)d_in[2];
    const float* att_src  = (const float*)d_in[3];
    const float* att_dst  = (const float*)d_in[4];
    const float* bias     = (const float*)d_in[5];
    float*       out      = (float*)d_out;
    int E = in_sizes[1] / 2;

    cudaFuncSetAttribute(gemm2_tc_kernel,
                         cudaFuncAttributeMaxDynamicSharedMemorySize,
                         2 * STAGE_BYTES);

    setup_kernel<<<41, 512>>>(ei, E, W, att_src, att_dst);
    xt_asrc_kernel<<<dim3(N_ / 128, G_), 256>>>(x);
    aggregate_kernel<<<dim3(N_ / 8, G_), 256>>>();
    gemm2_tc_kernel<<<dim3(N_ / 128, G_), 256, 2 * STAGE_BYTES>>>(bias, out);
}